// round 16
// baseline (speedup 1.0000x reference)
#include <cuda_runtime.h>
#include <cuda_fp16.h>
#include <cstdint>

#define B_  8
#define C_  512
#define H_  32
#define W_  32
#define NH_ 8
#define DH_ 64
#define HW_ 1024
#define C3_ (3*C_)

typedef __half h16;

// ---------------- scratch (device globals; no allocation allowed) ----------
__device__ h16   g_thi[(size_t)B_*HW_*C_];
__device__ h16   g_w1hi[(size_t)C3_*C_];
__device__ h16   g_w2hi[(size_t)C_*C_];
__device__ h16   g_w3hi[(size_t)C_*C_];
__device__ float g_psq[(size_t)B_*NH_*16*DH_];
__device__ float g_psk[(size_t)B_*NH_*16*DH_];
__device__ h16   g_qhi[(size_t)B_*NH_*HW_*DH_];
__device__ h16   g_khi[(size_t)B_*NH_*HW_*DH_];
__device__ h16   g_vhi[(size_t)B_*NH_*HW_*DH_];
__device__ h16   g_ohi[(size_t)B_*HW_*C_];
__device__ float g_ob [(size_t)B_*HW_*C_];
__device__ float g_y  [(size_t)B_*C_*HW_];
__device__ h16   g_dThi[(size_t)B_*HW_*C_];

// ---------------- small PTX helpers -----------------------------------------
__device__ __forceinline__ uint32_t smem_u32(const void* p) {
    uint32_t a;
    asm("{ .reg .u64 t; cvta.to.shared.u64 t, %1; cvt.u32.u64 %0, t; }"
        : "=r"(a) : "l"(p));
    return a;
}
__device__ __forceinline__ void cp16(uint32_t s, const void* g) {
    asm volatile("cp.async.cg.shared.global [%0], [%1], 16;" :: "r"(s), "l"(g));
}
#define SWZ(x) ((x) ^ (((x) >> 3) & 0x70u))

__device__ __forceinline__ void ldsm4(uint32_t* r, uint32_t addr) {
    asm volatile("ldmatrix.sync.aligned.m8n8.x4.shared.b16 {%0,%1,%2,%3}, [%4];"
                 : "=r"(r[0]), "=r"(r[1]), "=r"(r[2]), "=r"(r[3]) : "r"(addr));
}
__device__ __forceinline__ void ldsm4t(uint32_t* r, uint32_t addr) {
    asm volatile("ldmatrix.sync.aligned.m8n8.x4.trans.shared.b16 {%0,%1,%2,%3}, [%4];"
                 : "=r"(r[0]), "=r"(r[1]), "=r"(r[2]), "=r"(r[3]) : "r"(addr));
}
__device__ __forceinline__ void mma16816(float* c, const uint32_t* a,
                                         const uint32_t* b) {
    asm volatile(
        "mma.sync.aligned.m16n8k16.row.col.f32.f16.f16.f32 "
        "{%0,%1,%2,%3}, {%4,%5,%6,%7}, {%8,%9}, {%0,%1,%2,%3};"
        : "+f"(c[0]), "+f"(c[1]), "+f"(c[2]), "+f"(c[3])
        : "r"(a[0]), "r"(a[1]), "r"(a[2]), "r"(a[3]), "r"(b[0]), "r"(b[1]));
}
__device__ __forceinline__ uint32_t pack2(float a, float b) {
    __half2 h; h.x = __float2half(a); h.y = __float2half(b);
    return *(uint32_t*)&h;
}

// ---------------- HMMA GEMM: D = Ahi @ Bhi^T (1-term fp16), occ 2 ------------
#define GTB 16384u
#define GS1 (1024 + 2 * 2 * 16384)

__device__ __forceinline__ void load_chunk1(
    uint32_t dst, int tid, int m0, int n0, int K, int kc,
    const h16* __restrict__ Ahi, const h16* __restrict__ Bhi) {
#pragma unroll
    for (int it = 0; it < 4; it++) {
        int idx = it * 256 + tid;
        int r = idx >> 3, cg = idx & 7;
        uint32_t so = SWZ((uint32_t)(r * 128 + cg * 16));
        cp16(dst       + so, Ahi + (size_t)(m0 + r) * K + kc + cg * 8);
        cp16(dst + GTB + so, Bhi + (size_t)(n0 + r) * K + kc + cg * 8);
    }
    asm volatile("cp.async.commit_group;" ::: "memory");
}

__global__ __launch_bounds__(256, 2)
void gemm_tc(const h16* __restrict__ Ahi, const h16* __restrict__ Bhi,
             const float* __restrict__ bias, const float* __restrict__ resid,
             float* __restrict__ Cout, int K, int Nld,
             long bBatch, long cBatch, int mode) {
    extern __shared__ char smc[];
    uint32_t sb = smem_u32(smc);
    int tid = threadIdx.x, wid = tid >> 5, lane = tid & 31;
    int m0 = blockIdx.y * 128, n0 = blockIdx.x * 128;
    Bhi += (size_t)blockIdx.z * bBatch;
    if (Cout) Cout += (size_t)blockIdx.z * cBatch;
    const float* res = resid ? resid + (size_t)blockIdx.z * cBatch : nullptr;

    float* bsm = (float*)smc;
    if (tid < 128) bsm[tid] = bias ? bias[n0 + tid] : 0.f;

    const uint32_t t0 = sb + 1024;
    const uint32_t SS = 2u * GTB;
    const int nchunk = K >> 6;
    const int mb = (wid & 3) * 32;
    const int nb = (wid >> 2) * 64;

    float acc[2][8][4];
#pragma unroll
    for (int i = 0; i < 2; i++)
#pragma unroll
        for (int j = 0; j < 8; j++)
#pragma unroll
            for (int q = 0; q < 4; q++) acc[i][j][q] = 0.f;

    load_chunk1(t0, tid, m0, n0, K, 0, Ahi, Bhi);
    for (int c = 0; c < nchunk; c++) {
        asm volatile("cp.async.wait_group 0;" ::: "memory");
        __syncthreads();
        if (c + 1 < nchunk)
            load_chunk1(t0 + (uint32_t)((c + 1) & 1) * SS, tid, m0, n0, K,
                        (c + 1) << 6, Ahi, Bhi);
        uint32_t bufA = t0 + (uint32_t)(c & 1) * SS;
#pragma unroll
        for (int ks = 0; ks < 4; ks++) {
            int kb = ks * 32;
            uint32_t ao = SWZ((uint32_t)((mb + (lane & 15)) * 128 +
                                         (lane >> 4) * 16 + kb));
            uint32_t ahi[4];
            ldsm4(ahi, bufA + ao);
            uint32_t ao2 = SWZ((uint32_t)((mb + 16 + (lane & 15)) * 128 +
                                          (lane >> 4) * 16 + kb));
            uint32_t ahi2[4];
            ldsm4(ahi2, bufA + ao2);
            uint32_t brow = (uint32_t)((nb + (lane & 7) + ((lane >> 4) & 1) * 8) * 128 +
                                       ((lane >> 3) & 1) * 16 + kb);
#pragma unroll
            for (int ntp = 0; ntp < 4; ntp++) {
                uint32_t bo = SWZ(brow + (uint32_t)(ntp * 16 * 128));
                uint32_t bhi[4];
                ldsm4(bhi, bufA + GTB + bo);
#pragma unroll
                for (int half = 0; half < 2; half++) {
                    int ntile = ntp * 2 + half;
                    const uint32_t bh[2] = {bhi[half * 2], bhi[half * 2 + 1]};
                    mma16816(acc[0][ntile], ahi, bh);
                    mma16816(acc[1][ntile], ahi2, bh);
                }
            }
        }
    }

    int rbase = m0 + mb + (lane >> 2);
    int cbase = nb + (lane & 3) * 2;
#pragma unroll
    for (int mt = 0; mt < 2; mt++) {
#pragma unroll
        for (int ntile = 0; ntile < 8; ntile++) {
            int ncol = cbase + ntile * 8;
            int gcol = n0 + ncol;
#pragma unroll
            for (int rr = 0; rr < 2; rr++) {
                int row = rbase + mt * 16 + rr * 8;
                float v0 = acc[mt][ntile][rr * 2 + 0];
                float v1 = acc[mt][ntile][rr * 2 + 1];
                if (mode == 0) {
                    v0 += bsm[ncol]; v1 += bsm[ncol + 1];
                    size_t idx = (size_t)row * Nld + gcol;
                    if (res) {
                        float2 q = *(const float2*)(res + idx);
                        v0 += q.x; v1 += q.y;
                    }
                    float2 o; o.x = v0; o.y = v1;
                    *(float2*)(Cout + idx) = o;
                } else {
                    // qkv output: [bh][token][64] head-major, fp16
                    int b = row >> 10, tok = row & 1023;
                    int region = gcol >> 9;        // 0=q 1=k 2=v
                    int hd = gcol & 511;
                    int h = hd >> 6, d = hd & 63;
                    size_t dst = (((size_t)(b * NH_ + h) * HW_) + tok) * DH_ + d;
                    h16* ph = (region == 0) ? g_qhi : (region == 1) ? g_khi : g_vhi;
                    *(uint32_t*)&ph[dst] = pack2(v0, v1);
                }
            }
        }
    }
}

// ---------------- prep: vectorized weight fp16 conversion + build_t ----------
#define NW1 (C3_*C_)
#define NW2 (C_*C_)
#define NWTOT (NW1 + 2*NW2)
#define SPLIT_BLOCKS (NWTOT / 4 / 256)           // 1280
#define BT_BLOCKS    (B_ * (C_/32) * (HW_/32))   // 4096

__global__ void prep_kernel(const float* __restrict__ w1,
                            const float* __restrict__ w2,
                            const float* __restrict__ w3,
                            const float* __restrict__ x,
                            const float* __restrict__ pos,
                            h16* __restrict__ thi) {
    if (blockIdx.x < SPLIT_BLOCKS) {
        int i = (blockIdx.x * 256 + threadIdx.x) * 4;
        const float* src; h16* dst; int idx;
        if (i < NW1)            { src = w1; dst = g_w1hi; idx = i; }
        else if (i < NW1 + NW2) { src = w2; dst = g_w2hi; idx = i - NW1; }
        else                    { src = w3; dst = g_w3hi; idx = i - NW1 - NW2; }
        float4 v = *(const float4*)&src[idx];
        uint2 o;
        o.x = pack2(v.x, v.y);
        o.y = pack2(v.z, v.w);
        *(uint2*)&dst[idx] = o;
        return;
    }
    // build_t: transpose(x) + pos -> fp16
    __shared__ float tile[32][33];
    int bi = blockIdx.x - SPLIT_BLOCKS;
    int b  = bi >> 9;
    int rem = bi & 511;
    int c0 = (rem >> 5) * 32;
    int n0 = (rem & 31) * 32;
    int tx = threadIdx.x & 31, ty = threadIdx.x >> 5;  // 32 x 8
#pragma unroll
    for (int i = 0; i < 4; i++) {
        int c = c0 + ty + i * 8;
        tile[ty + i * 8][tx] = x[((size_t)b * C_ + c) * HW_ + n0 + tx];
    }
    __syncthreads();
#pragma unroll
    for (int i = 0; i < 4; i++) {
        int n = n0 + ty + i * 8;
        int c = c0 + tx;
        float v = tile[tx][ty + i * 8] + pos[(size_t)n * C_ + c];
        thi[((size_t)b * HW_ + n) * C_ + c] = __float2half(v);
    }
}

// ---------------- rs stage-1: uint4-vectorized partial norms -----------------
__global__ void rs1_kernel(float* __restrict__ psq, float* __restrict__ psk) {
    int bx = blockIdx.x;
    int bh = bx >> 4, part = bx & 15;
    int tid = threadIdx.x;
    int row = tid >> 3, g = tid & 7;   // 32 rows x 8 d-groups
    __shared__ float smq[32][64], smk[32][64];
    float aq[8] = {}, ak[8] = {};
    size_t base = (size_t)bh * HW_ * DH_;
    int n0 = part * 64;
#pragma unroll
    for (int p = 0; p < 2; p++) {
        int tok = n0 + p * 32 + row;
        size_t off = base + (size_t)tok * DH_ + g * 8;
        uint4 q4 = *(const uint4*)&g_qhi[off];
        uint4 k4 = *(const uint4*)&g_khi[off];
        uint32_t qw[4] = {q4.x, q4.y, q4.z, q4.w};
        uint32_t kw[4] = {k4.x, k4.y, k4.z, k4.w};
#pragma unroll
        for (int j = 0; j < 4; j++) {
            __half2 qh = *(__half2*)&qw[j];
            __half2 kh = *(__half2*)&kw[j];
            float a = __half2float(qh.x), b = __half2float(qh.y);
            aq[2 * j] += a * a; aq[2 * j + 1] += b * b;
            float c = __half2float(kh.x), d = __half2float(kh.y);
            ak[2 * j] += c * c; ak[2 * j + 1] += d * d;
        }
    }
#pragma unroll
    for (int j = 0; j < 8; j++) {
        smq[row][g * 8 + j] = aq[j];
        smk[row][g * 8 + j] = ak[j];
    }
    __syncthreads();
    if (tid < 64) {
        float q = 0.f, k = 0.f;
#pragma unroll
        for (int r = 0; r < 32; r++) { q += smq[r][tid]; k += smk[r][tid]; }
        psq[((size_t)bh * 16 + part) * 64 + tid] = q;
        psk[((size_t)bh * 16 + part) * 64 + tid] = k;
    }
}

// ---------------- tensor-core fused flash attention --------------------------
// Prologue computes rs from psq/psk (rs2 fused in). S = Qhi.Khi (1 MMA).
// P = exp(S) directly (logits bounded post-l2norm). O = Phi.Vhi (1 MMA).
#define FAT_STAGE 16384u
#define FAT_QOFF  32768u
#define FAT_SMEM  (32768 + 16384 + 256)

__device__ __forceinline__ void fat_loadkv(
    uint32_t buf, int tid, size_t kvbase, int kc,
    const h16* __restrict__ khi, const h16* __restrict__ vhi) {
#pragma unroll
    for (int it = 0; it < 2; it++) {
        int idx = it * 256 + tid;
        int r = idx >> 3, cg = idx & 7;
        uint32_t so = SWZ((uint32_t)(r * 128 + cg * 16));
        size_t g = kvbase + (size_t)(kc + r) * DH_ + cg * 8;
        cp16(buf +    0u + so, khi + g);
        cp16(buf + 8192u + so, vhi + g);
    }
    asm volatile("cp.async.commit_group;" ::: "memory");
}

__global__ __launch_bounds__(256, 2)
void fat_kernel(const h16* __restrict__ qhi,
                const float* __restrict__ temper,
                const float* __restrict__ psq, const float* __restrict__ psk,
                const h16* __restrict__ khi, const h16* __restrict__ vhi,
                h16* __restrict__ ohi) {
    extern __shared__ char smc[];
    uint32_t sb = smem_u32(smc);
    float* rss = (float*)(smc + FAT_QOFF + 16384);
    int bh = blockIdx.y;
    int b = bh >> 3, h = bh & 7;
    int q0 = blockIdx.x * 128;
    int tid = threadIdx.x, wid = tid >> 5, lane = tid & 31;
    int mb = wid * 16;

    const size_t kvbase = (size_t)bh * HW_ * DH_;
    fat_loadkv(sb, tid, kvbase, 0, khi, vhi);

    // fused rs2: reduce 16 partials -> rs scale (64 threads)
    if (tid < 64) {
        float q = 0.f, k = 0.f;
#pragma unroll
        for (int p = 0; p < 16; p++) {
            q += psq[((size_t)bh * 16 + p) * 64 + tid];
            k += psk[((size_t)bh * 16 + p) * 64 + tid];
        }
        float qn = fmaxf(sqrtf(q), 1e-12f);
        float kn = fmaxf(sqrtf(k), 1e-12f);
        rss[tid] = temper[h] / (qn * kn);
    }
    __syncthreads();

#pragma unroll
    for (int v = 0; v < 8; v++) {
        int idx = v * 256 + tid;
        int row = idx >> 4, dq = (idx & 15) * 4;
        size_t qoff = ((size_t)bh * HW_ + q0 + row) * DH_ + dq;
        __half2 ha = *(const __half2*)&qhi[qoff];
        __half2 hb = *(const __half2*)&qhi[qoff + 2];
        float qx = __half2float(ha.x) * rss[dq];
        float qy = __half2float(ha.y) * rss[dq + 1];
        float qz = __half2float(hb.x) * rss[dq + 2];
        float qw = __half2float(hb.y) * rss[dq + 3];
        uint32_t off = SWZ((uint32_t)(row * 128 + dq * 2));
        *(uint32_t*)(smc + FAT_QOFF + off)     = pack2(qx, qy);
        *(uint32_t*)(smc + FAT_QOFF + off + 4) = pack2(qz, qw);
    }

    float o[8][4];
#pragma unroll
    for (int j = 0; j < 8; j++)
#pragma unroll
        for (int q = 0; q < 4; q++) o[j][q] = 0.f;
    float l0 = 0.f, l1 = 0.f;

    for (int kt = 0; kt < 16; kt++) {
        asm volatile("cp.async.wait_group 0;" ::: "memory");
        __syncthreads();
        if (kt + 1 < 16)
            fat_loadkv(sb + (uint32_t)((kt + 1) & 1) * FAT_STAGE, tid, kvbase,
                       (kt + 1) * 64, khi, vhi);
        uint32_t cur = sb + (uint32_t)(kt & 1) * FAT_STAGE;

        // ---- S = Q.K^T
        float s[8][4];
#pragma unroll
        for (int j = 0; j < 8; j++)
#pragma unroll
            for (int q = 0; q < 4; q++) s[j][q] = 0.f;
#pragma unroll
        for (int ks = 0; ks < 4; ks++) {
            uint32_t qao = SWZ((uint32_t)((mb + (lane & 15)) * 128 +
                                          (lane >> 4) * 16 + ks * 32));
            uint32_t qh4[4];
            ldsm4(qh4, sb + FAT_QOFF + qao);
            uint32_t brow = (uint32_t)(((lane & 7) + ((lane >> 4) & 1) * 8) * 128 +
                                       ((lane >> 3) & 1) * 16 + ks * 32);
#pragma unroll
            for (int np = 0; np < 4; np++) {
                uint32_t bo = SWZ(brow + (uint32_t)(np * 16 * 128));
                uint32_t kh4[4];
                ldsm4(kh4, cur + bo);
#pragma unroll
                for (int half = 0; half < 2; half++) {
                    int j = np * 2 + half;
                    const uint32_t bhh[2] = {kh4[half * 2], kh4[half * 2 + 1]};
                    mma16816(s[j], qh4, bhh);
                }
            }
        }

        // ---- P = exp(S); accumulate row sums
        float sum0 = 0.f, sum1 = 0.f;
#pragma unroll
        for (int j = 0; j < 8; j++) {
            s[j][0] = __expf(s[j][0]);
            s[j][1] = __expf(s[j][1]);
            s[j][2] = __expf(s[j][2]);
            s[j][3] = __expf(s[j][3]);
            sum0 += s[j][0] + s[j][1];
            sum1 += s[j][2] + s[j][3];
        }
        l0 += sum0; l1 += sum1;

        // ---- O += Phi.Vhi
#pragma unroll
        for (int ks = 0; ks < 4; ks++) {
            int j0 = 2 * ks, j1 = 2 * ks + 1;
            uint32_t ph[4];
            ph[0] = pack2(s[j0][0], s[j0][1]);
            ph[1] = pack2(s[j0][2], s[j0][3]);
            ph[2] = pack2(s[j1][0], s[j1][1]);
            ph[3] = pack2(s[j1][2], s[j1][3]);
            uint32_t vrow = (uint32_t)((ks * 16 + (lane & 7) + ((lane >> 3) & 1) * 8) * 128 +
                                       ((lane >> 4) & 1) * 16);
#pragma unroll
            for (int np = 0; np < 4; np++) {
                uint32_t vo = SWZ(vrow + (uint32_t)(np * 32));
                uint32_t vh4[4];
                ldsm4t(vh4, cur + 8192u + vo);
#pragma unroll
                for (int half = 0; half < 2; half++) {
                    int j = np * 2 + half;
                    const uint32_t bvh[2] = {vh4[half * 2], vh4[half * 2 + 1]};
                    mma16816(o[j], ph, bvh);
                }
            }
        }
    }

    // finalize row sums across the quad, normalize, store fp16
    l0 += __shfl_xor_sync(0xffffffffu, l0, 1);
    l0 += __shfl_xor_sync(0xffffffffu, l0, 2);
    l1 += __shfl_xor_sync(0xffffffffu, l1, 1);
    l1 += __shfl_xor_sync(0xffffffffu, l1, 2);
    float inv0 = 1.f / l0, inv1 = 1.f / l1;
    int r0 = lane >> 2, cc = (lane & 3) * 2;
    int row0 = q0 + mb + r0, row1 = row0 + 8;
#pragma unroll
    for (int j = 0; j < 8; j++) {
        int col = h * DH_ + j * 8 + cc;
        size_t off0 = ((size_t)(b * HW_ + row0)) * C_ + col;
        size_t off1 = ((size_t)(b * HW_ + row1)) * C_ + col;
        *(uint32_t*)&ohi[off0] = pack2(o[j][0] * inv0, o[j][1] * inv0);
        *(uint32_t*)&ohi[off1] = pack2(o[j][2] * inv1, o[j][3] * inv1);
    }
}

// ---------------- LayerNorm over C + residual + transpose (warp-reduced) ----
__global__ void ln_residual_kernel(const float* __restrict__ ob,
                                   const float* __restrict__ x,
                                   const float* __restrict__ g,
                                   const float* __restrict__ be,
                                   float* __restrict__ y) {
    int row = blockIdx.x;
    int b = row >> 10, n = row & 1023;
    const float* pr = ob + (size_t)row * C_;
    int tid = threadIdx.x, lane = tid & 31, wid = tid >> 5;
    float v0 = pr[tid], v1 = pr[tid + 256];
    __shared__ float red[8];
    __shared__ float bc[2];

    float s = v0 + v1;
#pragma unroll
    for (int off = 16; off; off >>= 1) s += __shfl_xor_sync(0xffffffffu, s, off);
    if (lane == 0) red[wid] = s;
    __syncthreads();
    if (tid == 0) {
        float t = 0.f;
#pragma unroll
        for (int i = 0; i < 8; i++) t += red[i];
        bc[0] = t * (1.0f / C_);
    }
    __syncthreads();
    float mean = bc[0];
    float d0 = v0 - mean, d1 = v1 - mean;
    s = d0 * d0 + d1 * d1;
#pragma unroll
    for (int off = 16; off; off >>= 1) s += __shfl_xor_sync(0xffffffffu, s, off);
    if (lane == 0) red[wid] = s;
    __syncthreads();
    if (tid == 0) {
        float t = 0.f;
#pragma unroll
        for (int i = 0; i < 8; i++) t += red[i];
        bc[1] = rsqrtf(t * (1.0f / C_) + 1e-5f);
    }
    __syncthreads();
    float rstd = bc[1];
    int c0 = tid, c1 = tid + 256;
    size_t i0 = ((size_t)b * C_ + c0) * HW_ + n;
    size_t i1 = ((size_t)b * C_ + c1) * HW_ + n;
    y[i0] = d0 * rstd * g[c0] + be[c0] + x[i0];
    y[i1] = d1 * rstd * g[c1] + be[c1] + x[i1];
}

// ---------------- fused depthwise 3x3 + transpose -> fp16 --------------------
__global__ void dwt_kernel(const float* __restrict__ y,
                           const float* __restrict__ w,
                           const float* __restrict__ bias,
                           h16* __restrict__ hi) {
    __shared__ float yt[32][3][33];
    __shared__ float ot[32][33];   // [w][c]
    int hh = blockIdx.x, c0 = blockIdx.y * 32, b = blockIdx.z;
    int tid = threadIdx.x;
    int c = tid >> 3, wg = (tid & 7) * 4;

#pragma unroll
    for (int r = 0; r < 3; r++) {
        int ih = hh + r - 1;
        float4 v = make_float4(0.f, 0.f, 0.f, 0.f);
        if (ih >= 0 && ih < H_)
            v = *(const float4*)&y[((size_t)(b * C_ + c0 + c)) * HW_ + ih * W_ + wg];
        yt[c][r][wg + 0] = v.x; yt[c][r][wg + 1] = v.y;
        yt[c][r][wg + 2] = v.z; yt[c][r][wg + 3] = v.w;
    }
    float wc[9];
#pragma unroll
    for (int i = 0; i < 9; i++) wc[i] = w[(c0 + c) * 9 + i];
    float bs = bias[c0 + c];
    __syncthreads();

#pragma unroll
    for (int j = 0; j < 4; j++) {
        int ww = wg + j;
        float acc = bs;
#pragma unroll
        for (int ki = 0; ki < 3; ki++)
#pragma unroll
            for (int kj = 0; kj < 3; kj++) {
                int iw = ww + kj - 1;
                if (iw >= 0 && iw < W_) acc += wc[ki * 3 + kj] * yt[c][ki][iw];
            }
        ot[ww][c] = acc;
    }
    __syncthreads();

    int w2 = tid >> 3, cg = (tid & 7) * 4;
    int token = hh * W_ + w2;
    size_t base = ((size_t)b * HW_ + token) * C_ + c0 + cg;
    *(uint32_t*)&hi[base]     = pack2(ot[w2][cg],     ot[w2][cg + 1]);
    *(uint32_t*)&hi[base + 2] = pack2(ot[w2][cg + 2], ot[w2][cg + 3]);
}

// ---------------- launch ------------------------------------------------------
extern "C" void kernel_launch(void* const* d_in, const int* in_sizes, int n_in,
                              void* d_out, int out_size) {
    const float* x      = (const float*)d_in[0];
    const float* qkv_w  = (const float*)d_in[1];
    const float* proj_w = (const float*)d_in[2];
    const float* proj_b = (const float*)d_in[3];
    const float* temper = (const float*)d_in[4];
    const float* ln_g   = (const float*)d_in[5];
    const float* ln_b   = (const float*)d_in[6];
    const float* pos    = (const float*)d_in[7];
    const float* dw_w   = (const float*)d_in[8];
    const float* dw_b   = (const float*)d_in[9];
    const float* pw_w   = (const float*)d_in[10];
    const float* pw_b   = (const float*)d_in[11];
    float* out = (float*)d_out;

    h16 *thi, *w1hi, *w2hi, *w3hi;
    h16 *ohi, *dThi, *qhi, *khi, *vhi;
    float *ob, *y, *psq, *psk;
    cudaGetSymbolAddress((void**)&thi,  g_thi);
    cudaGetSymbolAddress((void**)&w1hi, g_w1hi);
    cudaGetSymbolAddress((void**)&w2hi, g_w2hi);
    cudaGetSymbolAddress((void**)&w3hi, g_w3hi);
    cudaGetSymbolAddress((void**)&ohi,  g_ohi);
    cudaGetSymbolAddress((void**)&dThi, g_dThi);
    cudaGetSymbolAddress((void**)&qhi,  g_qhi);
    cudaGetSymbolAddress((void**)&khi,  g_khi);
    cudaGetSymbolAddress((void**)&vhi,  g_vhi);
    cudaGetSymbolAddress((void**)&psq,  g_psq);
    cudaGetSymbolAddress((void**)&psk,  g_psk);
    cudaGetSymbolAddress((void**)&ob,   g_ob);
    cudaGetSymbolAddress((void**)&y,    g_y);

    cudaFuncSetAttribute(fat_kernel,
                         cudaFuncAttributeMaxDynamicSharedMemorySize, FAT_SMEM);
    cudaFuncSetAttribute(gemm_tc,
                         cudaFuncAttributeMaxDynamicSharedMemorySize, GS1);

    // prep: vectorized weight conversions + t = transpose(x)+pos (one launch)
    prep_kernel<<<SPLIT_BLOCKS + BT_BLOCKS, 256>>>(qkv_w, proj_w, pw_w,
                                                   x, pos, thi);
    // qkv GEMM: 1-term fp16, head-major split output (occ 2)
    gemm_tc<<<dim3(C3_/128, (B_*HW_)/128, 1), 256, GS1>>>(
        thi, w1hi, nullptr, nullptr, nullptr, C_, 0, 0, 0, 1);
    // rs stage-1 (stage-2 fused into fat prologue)
    rs1_kernel<<<B_*NH_*16, 256>>>(psq, psk);
    // tensor-core fused attention -> ohi
    fat_kernel<<<dim3(HW_/128, B_*NH_), 256, FAT_SMEM>>>(
        qhi, temper, psq, psk, khi, vhi, ohi);
    // proj = ohi @ w2hi^T + proj_b (1-term, occ 2)
    gemm_tc<<<dim3(C_/128, (B_*HW_)/128, 1), 256, GS1>>>(
        ohi, w2hi, proj_b, nullptr, ob, C_, C_, 0, 0, 0);
    // LN + residual + transpose to [B,C,HW]
    ln_residual_kernel<<<B_*HW_, 256>>>(ob, x, ln_g, ln_b, y);
    // fused depthwise 3x3 + transpose (fp16)
    dwt_kernel<<<dim3(H_, C_/32, B_), 256>>>(y, dw_w, dw_b, dThi);
    // pointwise (1-term, occ 2) + bias + residual -> out
    gemm_tc<<<dim3(HW_/128, C_/128, B_), 256, GS1>>>(
        w3hi, dThi, pw_b, y, out, C_, HW_,
        (long)HW_*C_, (long)C_*HW_, 0);
}

// round 17
// speedup vs baseline: 1.0148x; 1.0148x over previous
#include <cuda_runtime.h>
#include <cuda_fp16.h>
#include <cstdint>

#define B_  8
#define C_  512
#define H_  32
#define W_  32
#define NH_ 8
#define DH_ 64
#define HW_ 1024
#define C3_ (3*C_)

typedef __half h16;

// ---------------- scratch (device globals; no allocation allowed) ----------
__device__ h16   g_thi[(size_t)B_*HW_*C_];
__device__ h16   g_w1hi[(size_t)C3_*C_];
__device__ h16   g_w2hi[(size_t)C_*C_];
__device__ h16   g_w3hi[(size_t)C_*C_];
__device__ float g_psq[(size_t)B_*NH_*16*DH_];
__device__ float g_psk[(size_t)B_*NH_*16*DH_];
__device__ h16   g_qhi[(size_t)B_*NH_*HW_*DH_];
__device__ h16   g_khi[(size_t)B_*NH_*HW_*DH_];
__device__ h16   g_vhi[(size_t)B_*NH_*HW_*DH_];
__device__ h16   g_ohi[(size_t)B_*HW_*C_];
__device__ float g_ob [(size_t)B_*HW_*C_];
__device__ float g_y  [(size_t)B_*C_*HW_];
__device__ h16   g_dThi[(size_t)B_*HW_*C_];

// ---------------- small PTX helpers -----------------------------------------
__device__ __forceinline__ uint32_t smem_u32(const void* p) {
    uint32_t a;
    asm("{ .reg .u64 t; cvta.to.shared.u64 t, %1; cvt.u32.u64 %0, t; }"
        : "=r"(a) : "l"(p));
    return a;
}
__device__ __forceinline__ void cp16(uint32_t s, const void* g) {
    asm volatile("cp.async.cg.shared.global [%0], [%1], 16;" :: "r"(s), "l"(g));
}
#define SWZ(x) ((x) ^ (((x) >> 3) & 0x70u))

__device__ __forceinline__ void ldsm4(uint32_t* r, uint32_t addr) {
    asm volatile("ldmatrix.sync.aligned.m8n8.x4.shared.b16 {%0,%1,%2,%3}, [%4];"
                 : "=r"(r[0]), "=r"(r[1]), "=r"(r[2]), "=r"(r[3]) : "r"(addr));
}
__device__ __forceinline__ void ldsm4t(uint32_t* r, uint32_t addr) {
    asm volatile("ldmatrix.sync.aligned.m8n8.x4.trans.shared.b16 {%0,%1,%2,%3}, [%4];"
                 : "=r"(r[0]), "=r"(r[1]), "=r"(r[2]), "=r"(r[3]) : "r"(addr));
}
__device__ __forceinline__ void mma16816(float* c, const uint32_t* a,
                                         const uint32_t* b) {
    asm volatile(
        "mma.sync.aligned.m16n8k16.row.col.f32.f16.f16.f32 "
        "{%0,%1,%2,%3}, {%4,%5,%6,%7}, {%8,%9}, {%0,%1,%2,%3};"
        : "+f"(c[0]), "+f"(c[1]), "+f"(c[2]), "+f"(c[3])
        : "r"(a[0]), "r"(a[1]), "r"(a[2]), "r"(a[3]), "r"(b[0]), "r"(b[1]));
}
__device__ __forceinline__ uint32_t pack2(float a, float b) {
    __half2 h; h.x = __float2half(a); h.y = __float2half(b);
    return *(uint32_t*)&h;
}
__device__ __forceinline__ float ex2(float x) {
    float y;
    asm("ex2.approx.f32 %0, %1;" : "=f"(y) : "f"(x));
    return y;
}

// ---------------- HMMA GEMM: D = Ahi @ Bhi^T (1-term fp16), occ 2 ------------
#define GTB 16384u
#define GS1 (1024 + 2 * 2 * 16384)

__device__ __forceinline__ void load_chunk1(
    uint32_t dst, int tid, int m0, int n0, int K, int kc,
    const h16* __restrict__ Ahi, const h16* __restrict__ Bhi) {
#pragma unroll
    for (int it = 0; it < 4; it++) {
        int idx = it * 256 + tid;
        int r = idx >> 3, cg = idx & 7;
        uint32_t so = SWZ((uint32_t)(r * 128 + cg * 16));
        cp16(dst       + so, Ahi + (size_t)(m0 + r) * K + kc + cg * 8);
        cp16(dst + GTB + so, Bhi + (size_t)(n0 + r) * K + kc + cg * 8);
    }
    asm volatile("cp.async.commit_group;" ::: "memory");
}

__global__ __launch_bounds__(256, 2)
void gemm_tc(const h16* __restrict__ Ahi, const h16* __restrict__ Bhi,
             const float* __restrict__ bias, const float* __restrict__ resid,
             float* __restrict__ Cout, int K, int Nld,
             long bBatch, long cBatch, int mode) {
    extern __shared__ char smc[];
    uint32_t sb = smem_u32(smc);
    int tid = threadIdx.x, wid = tid >> 5, lane = tid & 31;
    int m0 = blockIdx.y * 128, n0 = blockIdx.x * 128;
    Bhi += (size_t)blockIdx.z * bBatch;
    if (Cout) Cout += (size_t)blockIdx.z * cBatch;
    const float* res = resid ? resid + (size_t)blockIdx.z * cBatch : nullptr;

    float* bsm = (float*)smc;
    if (tid < 128) bsm[tid] = bias ? bias[n0 + tid] : 0.f;

    const uint32_t t0 = sb + 1024;
    const uint32_t SS = 2u * GTB;
    const int nchunk = K >> 6;
    const int mb = (wid & 3) * 32;
    const int nb = (wid >> 2) * 64;

    float acc[2][8][4];
#pragma unroll
    for (int i = 0; i < 2; i++)
#pragma unroll
        for (int j = 0; j < 8; j++)
#pragma unroll
            for (int q = 0; q < 4; q++) acc[i][j][q] = 0.f;

    load_chunk1(t0, tid, m0, n0, K, 0, Ahi, Bhi);
    for (int c = 0; c < nchunk; c++) {
        asm volatile("cp.async.wait_group 0;" ::: "memory");
        __syncthreads();
        if (c + 1 < nchunk)
            load_chunk1(t0 + (uint32_t)((c + 1) & 1) * SS, tid, m0, n0, K,
                        (c + 1) << 6, Ahi, Bhi);
        uint32_t bufA = t0 + (uint32_t)(c & 1) * SS;
#pragma unroll
        for (int ks = 0; ks < 4; ks++) {
            int kb = ks * 32;
            uint32_t ao = SWZ((uint32_t)((mb + (lane & 15)) * 128 +
                                         (lane >> 4) * 16 + kb));
            uint32_t ahi[4];
            ldsm4(ahi, bufA + ao);
            uint32_t ao2 = SWZ((uint32_t)((mb + 16 + (lane & 15)) * 128 +
                                          (lane >> 4) * 16 + kb));
            uint32_t ahi2[4];
            ldsm4(ahi2, bufA + ao2);
            uint32_t brow = (uint32_t)((nb + (lane & 7) + ((lane >> 4) & 1) * 8) * 128 +
                                       ((lane >> 3) & 1) * 16 + kb);
#pragma unroll
            for (int ntp = 0; ntp < 4; ntp++) {
                uint32_t bo = SWZ(brow + (uint32_t)(ntp * 16 * 128));
                uint32_t bhi[4];
                ldsm4(bhi, bufA + GTB + bo);
#pragma unroll
                for (int half = 0; half < 2; half++) {
                    int ntile = ntp * 2 + half;
                    const uint32_t bh[2] = {bhi[half * 2], bhi[half * 2 + 1]};
                    mma16816(acc[0][ntile], ahi, bh);
                    mma16816(acc[1][ntile], ahi2, bh);
                }
            }
        }
    }

    int rbase = m0 + mb + (lane >> 2);
    int cbase = nb + (lane & 3) * 2;
#pragma unroll
    for (int mt = 0; mt < 2; mt++) {
#pragma unroll
        for (int ntile = 0; ntile < 8; ntile++) {
            int ncol = cbase + ntile * 8;
            int gcol = n0 + ncol;
#pragma unroll
            for (int rr = 0; rr < 2; rr++) {
                int row = rbase + mt * 16 + rr * 8;
                float v0 = acc[mt][ntile][rr * 2 + 0];
                float v1 = acc[mt][ntile][rr * 2 + 1];
                if (mode == 0) {
                    v0 += bsm[ncol]; v1 += bsm[ncol + 1];
                    size_t idx = (size_t)row * Nld + gcol;
                    if (res) {
                        float2 q = *(const float2*)(res + idx);
                        v0 += q.x; v1 += q.y;
                    }
                    float2 o; o.x = v0; o.y = v1;
                    *(float2*)(Cout + idx) = o;
                } else {
                    // qkv output: [bh][token][64] head-major, fp16
                    int b = row >> 10, tok = row & 1023;
                    int region = gcol >> 9;        // 0=q 1=k 2=v
                    int hd = gcol & 511;
                    int h = hd >> 6, d = hd & 63;
                    size_t dst = (((size_t)(b * NH_ + h) * HW_) + tok) * DH_ + d;
                    h16* ph = (region == 0) ? g_qhi : (region == 1) ? g_khi : g_vhi;
                    *(uint32_t*)&ph[dst] = pack2(v0, v1);
                }
            }
        }
    }
}

// ---------------- prep: vectorized weight fp16 conversion + build_t ----------
#define NW1 (C3_*C_)
#define NW2 (C_*C_)
#define NWTOT (NW1 + 2*NW2)
#define SPLIT_BLOCKS (NWTOT / 4 / 256)           // 1280
#define BT_BLOCKS    (B_ * (C_/32) * (HW_/32))   // 4096

__global__ void prep_kernel(const float* __restrict__ w1,
                            const float* __restrict__ w2,
                            const float* __restrict__ w3,
                            const float* __restrict__ x,
                            const float* __restrict__ pos,
                            h16* __restrict__ thi) {
    if (blockIdx.x < SPLIT_BLOCKS) {
        int i = (blockIdx.x * 256 + threadIdx.x) * 4;
        const float* src; h16* dst; int idx;
        if (i < NW1)            { src = w1; dst = g_w1hi; idx = i; }
        else if (i < NW1 + NW2) { src = w2; dst = g_w2hi; idx = i - NW1; }
        else                    { src = w3; dst = g_w3hi; idx = i - NW1 - NW2; }
        float4 v = *(const float4*)&src[idx];
        uint2 o;
        o.x = pack2(v.x, v.y);
        o.y = pack2(v.z, v.w);
        *(uint2*)&dst[idx] = o;
        return;
    }
    // build_t: transpose(x) + pos -> fp16
    __shared__ float tile[32][33];
    int bi = blockIdx.x - SPLIT_BLOCKS;
    int b  = bi >> 9;
    int rem = bi & 511;
    int c0 = (rem >> 5) * 32;
    int n0 = (rem & 31) * 32;
    int tx = threadIdx.x & 31, ty = threadIdx.x >> 5;  // 32 x 8
#pragma unroll
    for (int i = 0; i < 4; i++) {
        int c = c0 + ty + i * 8;
        tile[ty + i * 8][tx] = x[((size_t)b * C_ + c) * HW_ + n0 + tx];
    }
    __syncthreads();
#pragma unroll
    for (int i = 0; i < 4; i++) {
        int n = n0 + ty + i * 8;
        int c = c0 + tx;
        float v = tile[tx][ty + i * 8] + pos[(size_t)n * C_ + c];
        thi[((size_t)b * HW_ + n) * C_ + c] = __float2half(v);
    }
}

// ---------------- rs stage-1: uint4-vectorized partial norms -----------------
__global__ void rs1_kernel(float* __restrict__ psq, float* __restrict__ psk) {
    int bx = blockIdx.x;
    int bh = bx >> 4, part = bx & 15;
    int tid = threadIdx.x;
    int row = tid >> 3, g = tid & 7;   // 32 rows x 8 d-groups
    __shared__ float smq[32][64], smk[32][64];
    float aq[8] = {}, ak[8] = {};
    size_t base = (size_t)bh * HW_ * DH_;
    int n0 = part * 64;
#pragma unroll
    for (int p = 0; p < 2; p++) {
        int tok = n0 + p * 32 + row;
        size_t off = base + (size_t)tok * DH_ + g * 8;
        uint4 q4 = *(const uint4*)&g_qhi[off];
        uint4 k4 = *(const uint4*)&g_khi[off];
        uint32_t qw[4] = {q4.x, q4.y, q4.z, q4.w};
        uint32_t kw[4] = {k4.x, k4.y, k4.z, k4.w};
#pragma unroll
        for (int j = 0; j < 4; j++) {
            __half2 qh = *(__half2*)&qw[j];
            __half2 kh = *(__half2*)&kw[j];
            float a = __half2float(qh.x), b = __half2float(qh.y);
            aq[2 * j] += a * a; aq[2 * j + 1] += b * b;
            float c = __half2float(kh.x), d = __half2float(kh.y);
            ak[2 * j] += c * c; ak[2 * j + 1] += d * d;
        }
    }
#pragma unroll
    for (int j = 0; j < 8; j++) {
        smq[row][g * 8 + j] = aq[j];
        smk[row][g * 8 + j] = ak[j];
    }
    __syncthreads();
    if (tid < 64) {
        float q = 0.f, k = 0.f;
#pragma unroll
        for (int r = 0; r < 32; r++) { q += smq[r][tid]; k += smk[r][tid]; }
        psq[((size_t)bh * 16 + part) * 64 + tid] = q;
        psk[((size_t)bh * 16 + part) * 64 + tid] = k;
    }
}

// ---------------- tensor-core fused flash attention --------------------------
// Prologue computes rs (with log2e folded). S = Qhi.Khi (1 MMA).
// P = ex2(S) (= exp of unscaled logits; bounded post-l2norm). O = Phi.Vhi.
#define FAT_STAGE 16384u
#define FAT_QOFF  32768u
#define FAT_SMEM  (32768 + 16384 + 256)

__device__ __forceinline__ void fat_loadkv(
    uint32_t buf, int tid, size_t kvbase, int kc,
    const h16* __restrict__ khi, const h16* __restrict__ vhi) {
#pragma unroll
    for (int it = 0; it < 2; it++) {
        int idx = it * 256 + tid;
        int r = idx >> 3, cg = idx & 7;
        uint32_t so = SWZ((uint32_t)(r * 128 + cg * 16));
        size_t g = kvbase + (size_t)(kc + r) * DH_ + cg * 8;
        cp16(buf +    0u + so, khi + g);
        cp16(buf + 8192u + so, vhi + g);
    }
    asm volatile("cp.async.commit_group;" ::: "memory");
}

__global__ __launch_bounds__(256, 2)
void fat_kernel(const h16* __restrict__ qhi,
                const float* __restrict__ temper,
                const float* __restrict__ psq, const float* __restrict__ psk,
                const h16* __restrict__ khi, const h16* __restrict__ vhi,
                h16* __restrict__ ohi) {
    extern __shared__ char smc[];
    uint32_t sb = smem_u32(smc);
    float* rss = (float*)(smc + FAT_QOFF + 16384);
    int bh = blockIdx.y;
    int b = bh >> 3, h = bh & 7;
    int q0 = blockIdx.x * 128;
    int tid = threadIdx.x, wid = tid >> 5, lane = tid & 31;
    int mb = wid * 16;

    const size_t kvbase = (size_t)bh * HW_ * DH_;
    fat_loadkv(sb, tid, kvbase, 0, khi, vhi);

    // fused rs2: reduce 16 partials -> rs scale * log2(e) (64 threads)
    if (tid < 64) {
        float q = 0.f, k = 0.f;
#pragma unroll
        for (int p = 0; p < 16; p++) {
            q += psq[((size_t)bh * 16 + p) * 64 + tid];
            k += psk[((size_t)bh * 16 + p) * 64 + tid];
        }
        float qn = fmaxf(sqrtf(q), 1e-12f);
        float kn = fmaxf(sqrtf(k), 1e-12f);
        rss[tid] = temper[h] * 1.4426950408889634f / (qn * kn);
    }
    __syncthreads();

    // stage Q (scaled by rs*log2e) fp16 into persistent smem (uint4 loads)
#pragma unroll
    for (int v = 0; v < 4; v++) {
        int idx = v * 256 + tid;
        int row = idx >> 3, dq = (idx & 7) * 8;
        size_t qoff = ((size_t)bh * HW_ + q0 + row) * DH_ + dq;
        uint4 q4 = *(const uint4*)&qhi[qoff];
        uint32_t qw[4] = {q4.x, q4.y, q4.z, q4.w};
        uint32_t ow[4];
#pragma unroll
        for (int j = 0; j < 4; j++) {
            __half2 hh = *(__half2*)&qw[j];
            ow[j] = pack2(__half2float(hh.x) * rss[dq + 2 * j],
                          __half2float(hh.y) * rss[dq + 2 * j + 1]);
        }
        uint32_t off = SWZ((uint32_t)(row * 128 + dq * 2));
        *(uint2*)(smc + FAT_QOFF + off)     = make_uint2(ow[0], ow[1]);
        *(uint2*)(smc + FAT_QOFF + off + 8) = make_uint2(ow[2], ow[3]);
    }

    float o[8][4];
#pragma unroll
    for (int j = 0; j < 8; j++)
#pragma unroll
        for (int q = 0; q < 4; q++) o[j][q] = 0.f;
    float l0 = 0.f, l1 = 0.f;

    for (int kt = 0; kt < 16; kt++) {
        asm volatile("cp.async.wait_group 0;" ::: "memory");
        __syncthreads();
        if (kt + 1 < 16)
            fat_loadkv(sb + (uint32_t)((kt + 1) & 1) * FAT_STAGE, tid, kvbase,
                       (kt + 1) * 64, khi, vhi);
        uint32_t cur = sb + (uint32_t)(kt & 1) * FAT_STAGE;

        // ---- S = Q.K^T (logits pre-scaled by log2e)
        float s[8][4];
#pragma unroll
        for (int j = 0; j < 8; j++)
#pragma unroll
            for (int q = 0; q < 4; q++) s[j][q] = 0.f;
#pragma unroll
        for (int ks = 0; ks < 4; ks++) {
            uint32_t qao = SWZ((uint32_t)((mb + (lane & 15)) * 128 +
                                          (lane >> 4) * 16 + ks * 32));
            uint32_t qh4[4];
            ldsm4(qh4, sb + FAT_QOFF + qao);
            uint32_t brow = (uint32_t)(((lane & 7) + ((lane >> 4) & 1) * 8) * 128 +
                                       ((lane >> 3) & 1) * 16 + ks * 32);
#pragma unroll
            for (int np = 0; np < 4; np++) {
                uint32_t bo = SWZ(brow + (uint32_t)(np * 16 * 128));
                uint32_t kh4[4];
                ldsm4(kh4, cur + bo);
#pragma unroll
                for (int half = 0; half < 2; half++) {
                    int j = np * 2 + half;
                    const uint32_t bhh[2] = {kh4[half * 2], kh4[half * 2 + 1]};
                    mma16816(s[j], qh4, bhh);
                }
            }
        }

        // ---- P = 2^S (single MUFU each); accumulate row sums
        float sum0 = 0.f, sum1 = 0.f;
#pragma unroll
        for (int j = 0; j < 8; j++) {
            s[j][0] = ex2(s[j][0]);
            s[j][1] = ex2(s[j][1]);
            s[j][2] = ex2(s[j][2]);
            s[j][3] = ex2(s[j][3]);
            sum0 += s[j][0] + s[j][1];
            sum1 += s[j][2] + s[j][3];
        }
        l0 += sum0; l1 += sum1;

        // ---- O += Phi.Vhi
#pragma unroll
        for (int ks = 0; ks < 4; ks++) {
            int j0 = 2 * ks, j1 = 2 * ks + 1;
            uint32_t ph[4];
            ph[0] = pack2(s[j0][0], s[j0][1]);
            ph[1] = pack2(s[j0][2], s[j0][3]);
            ph[2] = pack2(s[j1][0], s[j1][1]);
            ph[3] = pack2(s[j1][2], s[j1][3]);
            uint32_t vrow = (uint32_t)((ks * 16 + (lane & 7) + ((lane >> 3) & 1) * 8) * 128 +
                                       ((lane >> 4) & 1) * 16);
#pragma unroll
            for (int np = 0; np < 4; np++) {
                uint32_t vo = SWZ(vrow + (uint32_t)(np * 32));
                uint32_t vh4[4];
                ldsm4t(vh4, cur + 8192u + vo);
#pragma unroll
                for (int half = 0; half < 2; half++) {
                    int j = np * 2 + half;
                    const uint32_t bvh[2] = {vh4[half * 2], vh4[half * 2 + 1]};
                    mma16816(o[j], ph, bvh);
                }
            }
        }
    }

    // finalize row sums across the quad, normalize, store fp16
    l0 += __shfl_xor_sync(0xffffffffu, l0, 1);
    l0 += __shfl_xor_sync(0xffffffffu, l0, 2);
    l1 += __shfl_xor_sync(0xffffffffu, l1, 1);
    l1 += __shfl_xor_sync(0xffffffffu, l1, 2);
    float inv0 = 1.f / l0, inv1 = 1.f / l1;
    int r0 = lane >> 2, cc = (lane & 3) * 2;
    int row0 = q0 + mb + r0, row1 = row0 + 8;
#pragma unroll
    for (int j = 0; j < 8; j++) {
        int col = h * DH_ + j * 8 + cc;
        size_t off0 = ((size_t)(b * HW_ + row0)) * C_ + col;
        size_t off1 = ((size_t)(b * HW_ + row1)) * C_ + col;
        *(uint32_t*)&ohi[off0] = pack2(o[j][0] * inv0, o[j][1] * inv0);
        *(uint32_t*)&ohi[off1] = pack2(o[j][2] * inv1, o[j][3] * inv1);
    }
}

// ---------------- LayerNorm over C + residual + transpose (warp-reduced) ----
__global__ void ln_residual_kernel(const float* __restrict__ ob,
                                   const float* __restrict__ x,
                                   const float* __restrict__ g,
                                   const float* __restrict__ be,
                                   float* __restrict__ y) {
    int row = blockIdx.x;
    int b = row >> 10, n = row & 1023;
    const float* pr = ob + (size_t)row * C_;
    int tid = threadIdx.x, lane = tid & 31, wid = tid >> 5;
    float v0 = pr[tid], v1 = pr[tid + 256];
    __shared__ float red[8];
    __shared__ float bc[2];

    float s = v0 + v1;
#pragma unroll
    for (int off = 16; off; off >>= 1) s += __shfl_xor_sync(0xffffffffu, s, off);
    if (lane == 0) red[wid] = s;
    __syncthreads();
    if (tid == 0) {
        float t = 0.f;
#pragma unroll
        for (int i = 0; i < 8; i++) t += red[i];
        bc[0] = t * (1.0f / C_);
    }
    __syncthreads();
    float mean = bc[0];
    float d0 = v0 - mean, d1 = v1 - mean;
    s = d0 * d0 + d1 * d1;
#pragma unroll
    for (int off = 16; off; off >>= 1) s += __shfl_xor_sync(0xffffffffu, s, off);
    if (lane == 0) red[wid] = s;
    __syncthreads();
    if (tid == 0) {
        float t = 0.f;
#pragma unroll
        for (int i = 0; i < 8; i++) t += red[i];
        bc[1] = rsqrtf(t * (1.0f / C_) + 1e-5f);
    }
    __syncthreads();
    float rstd = bc[1];
    int c0 = tid, c1 = tid + 256;
    size_t i0 = ((size_t)b * C_ + c0) * HW_ + n;
    size_t i1 = ((size_t)b * C_ + c1) * HW_ + n;
    y[i0] = d0 * rstd * g[c0] + be[c0] + x[i0];
    y[i1] = d1 * rstd * g[c1] + be[c1] + x[i1];
}

// ---------------- fused depthwise 3x3 + transpose -> fp16 --------------------
__global__ void dwt_kernel(const float* __restrict__ y,
                           const float* __restrict__ w,
                           const float* __restrict__ bias,
                           h16* __restrict__ hi) {
    __shared__ float yt[32][3][33];
    __shared__ float ot[32][33];   // [w][c]
    int hh = blockIdx.x, c0 = blockIdx.y * 32, b = blockIdx.z;
    int tid = threadIdx.x;
    int c = tid >> 3, wg = (tid & 7) * 4;

#pragma unroll
    for (int r = 0; r < 3; r++) {
        int ih = hh + r - 1;
        float4 v = make_float4(0.f, 0.f, 0.f, 0.f);
        if (ih >= 0 && ih < H_)
            v = *(const float4*)&y[((size_t)(b * C_ + c0 + c)) * HW_ + ih * W_ + wg];
        yt[c][r][wg + 0] = v.x; yt[c][r][wg + 1] = v.y;
        yt[c][r][wg + 2] = v.z; yt[c][r][wg + 3] = v.w;
    }
    float wc[9];
#pragma unroll
    for (int i = 0; i < 9; i++) wc[i] = w[(c0 + c) * 9 + i];
    float bs = bias[c0 + c];
    __syncthreads();

#pragma unroll
    for (int j = 0; j < 4; j++) {
        int ww = wg + j;
        float acc = bs;
#pragma unroll
        for (int ki = 0; ki < 3; ki++)
#pragma unroll
            for (int kj = 0; kj < 3; kj++) {
                int iw = ww + kj - 1;
                if (iw >= 0 && iw < W_) acc += wc[ki * 3 + kj] * yt[c][ki][iw];
            }
        ot[ww][c] = acc;
    }
    __syncthreads();

    int w2 = tid >> 3, cg = (tid & 7) * 4;
    int token = hh * W_ + w2;
    size_t base = ((size_t)b * HW_ + token) * C_ + c0 + cg;
    *(uint32_t*)&hi[base]     = pack2(ot[w2][cg],     ot[w2][cg + 1]);
    *(uint32_t*)&hi[base + 2] = pack2(ot[w2][cg + 2], ot[w2][cg + 3]);
}

// ---------------- launch ------------------------------------------------------
extern "C" void kernel_launch(void* const* d_in, const int* in_sizes, int n_in,
                              void* d_out, int out_size) {
    const float* x      = (const float*)d_in[0];
    const float* qkv_w  = (const float*)d_in[1];
    const float* proj_w = (const float*)d_in[2];
    const float* proj_b = (const float*)d_in[3];
    const float* temper = (const float*)d_in[4];
    const float* ln_g   = (const float*)d_in[5];
    const float* ln_b   = (const float*)d_in[6];
    const float* pos    = (const float*)d_in[7];
    const float* dw_w   = (const float*)d_in[8];
    const float* dw_b   = (const float*)d_in[9];
    const float* pw_w   = (const float*)d_in[10];
    const float* pw_b   = (const float*)d_in[11];
    float* out = (float*)d_out;

    h16 *thi, *w1hi, *w2hi, *w3hi;
    h16 *ohi, *dThi, *qhi, *khi, *vhi;
    float *ob, *y, *psq, *psk;
    cudaGetSymbolAddress((void**)&thi,  g_thi);
    cudaGetSymbolAddress((void**)&w1hi, g_w1hi);
    cudaGetSymbolAddress((void**)&w2hi, g_w2hi);
    cudaGetSymbolAddress((void**)&w3hi, g_w3hi);
    cudaGetSymbolAddress((void**)&ohi,  g_ohi);
    cudaGetSymbolAddress((void**)&dThi, g_dThi);
    cudaGetSymbolAddress((void**)&qhi,  g_qhi);
    cudaGetSymbolAddress((void**)&khi,  g_khi);
    cudaGetSymbolAddress((void**)&vhi,  g_vhi);
    cudaGetSymbolAddress((void**)&psq,  g_psq);
    cudaGetSymbolAddress((void**)&psk,  g_psk);
    cudaGetSymbolAddress((void**)&ob,   g_ob);
    cudaGetSymbolAddress((void**)&y,    g_y);

    cudaFuncSetAttribute(fat_kernel,
                         cudaFuncAttributeMaxDynamicSharedMemorySize, FAT_SMEM);
    cudaFuncSetAttribute(gemm_tc,
                         cudaFuncAttributeMaxDynamicSharedMemorySize, GS1);

    // prep: vectorized weight conversions + t = transpose(x)+pos (one launch)
    prep_kernel<<<SPLIT_BLOCKS + BT_BLOCKS, 256>>>(qkv_w, proj_w, pw_w,
                                                   x, pos, thi);
    // qkv GEMM: 1-term fp16, head-major split output (occ 2)
    gemm_tc<<<dim3(C3_/128, (B_*HW_)/128, 1), 256, GS1>>>(
        thi, w1hi, nullptr, nullptr, nullptr, C_, 0, 0, 0, 1);
    // rs stage-1 (stage-2 fused into fat prologue)
    rs1_kernel<<<B_*NH_*16, 256>>>(psq, psk);
    // tensor-core fused attention -> ohi
    fat_kernel<<<dim3(HW_/128, B_*NH_), 256, FAT_SMEM>>>(
        qhi, temper, psq, psk, khi, vhi, ohi);
    // proj = ohi @ w2hi^T + proj_b (1-term, occ 2)
    gemm_tc<<<dim3(C_/128, (B_*HW_)/128, 1), 256, GS1>>>(
        ohi, w2hi, proj_b, nullptr, ob, C_, C_, 0, 0, 0);
    // LN + residual + transpose to [B,C,HW]
    ln_residual_kernel<<<B_*HW_, 256>>>(ob, x, ln_g, ln_b, y);
    // fused depthwise 3x3 + transpose (fp16)
    dwt_kernel<<<dim3(H_, C_/32, B_), 256>>>(y, dw_w, dw_b, dThi);
    // pointwise (1-term, occ 2) + bias + residual -> out
    gemm_tc<<<dim3(HW_/128, C_/128, B_), 256, GS1>>>(
        w3hi, dThi, pw_b, y, out, C_, HW_,
        (long)HW_*C_, (long)C_*HW_, 0);
}